// round 5
// baseline (speedup 1.0000x reference)
#include <cuda_runtime.h>
#include <cuda_bf16.h>
#include <cstdint>

// Problem constants
#define NN   10000      // nodes
#define INF  10000      // input features
#define HID  128
#define EMAX 320000

// ---------------- scratch (device globals; no allocation allowed) ----------------
__device__ float g_h[NN * HID];          // h = x @ W_conv
__device__ float g_deg[NN];
__device__ float g_dinv[NN];
__device__ int   g_cnt[NN];
__device__ int   g_base[NN + 1];
__device__ int   g_cursor[NN];
__device__ int   g_sr[EMAX];             // CSR-by-col: source node per edge
__device__ float g_sw[EMAX];             // CSR-by-col: norm weight per edge
__device__ int   g_is64;                 // edge_index dtype flag (1 = int64, 0 = int32)

// ---------------- small helpers ----------------
__device__ __forceinline__ unsigned f2tf(float f) {
    unsigned u;
    asm("cvt.rna.tf32.f32 %0, %1;" : "=r"(u) : "f"(f));
    return u;
}

__device__ __forceinline__ int load_edge_idx(const void* ei, int is64, long long pos) {
    if (is64) return (int)((const long long*)ei)[pos];
    return ((const int*)ei)[pos];
}

__device__ __forceinline__ void cp_async16(void* smem_dst, const void* gmem_src, int valid_bytes) {
    unsigned saddr = (unsigned)__cvta_generic_to_shared(smem_dst);
    asm volatile("cp.async.cg.shared.global [%0], [%1], 16, %2;\n"
                 :: "r"(saddr), "l"(gmem_src), "r"(valid_bytes));
}

__device__ __forceinline__ void mma_tf32(float c[4], const unsigned a[4], const unsigned b[2]) {
    asm volatile(
        "mma.sync.aligned.m16n8k8.row.col.f32.tf32.tf32.f32 "
        "{%0,%1,%2,%3}, {%4,%5,%6,%7}, {%8,%9}, {%0,%1,%2,%3};\n"
        : "+f"(c[0]), "+f"(c[1]), "+f"(c[2]), "+f"(c[3])
        : "r"(a[0]), "r"(a[1]), "r"(a[2]), "r"(a[3]), "r"(b[0]), "r"(b[1]));
}

// ---------------- kernel 1: init ----------------
__global__ void k_init() {
    int i = blockIdx.x * blockDim.x + threadIdx.x;
    if (i < NN) {
        g_deg[i] = 1.0f;   // self-loop weight
        g_cnt[i] = 0;
        g_cursor[i] = 0;
    }
    if (i == 0) g_is64 = 1;
}

// ---------------- kernel 1b: detect edge_index dtype ----------------
// Reads only the first 2E int32 words — in-bounds whether the buffer holds
// 2E int32s or 2E int64s. If int64, every odd word is a zero high-half
// (indices < 2^31). If int32, odd words are node ids; some are nonzero with
// overwhelming probability. Any nonzero odd word => int32.
__global__ void k_detect(const int* __restrict__ ei_words, int E) {
    int t = blockIdx.x * blockDim.x + threadIdx.x;
    long long idx = 2LL * t + 1;           // odd word positions
    if (idx < 2LL * E) {
        if (ei_words[idx] != 0) g_is64 = 0;
    }
}

// ---------------- kernel 2: degree + count ----------------
__global__ void k_count(const void* __restrict__ ei, const float* __restrict__ ew, int E) {
    int e = blockIdx.x * blockDim.x + threadIdx.x;
    if (e >= E) return;
    int is64 = g_is64;
    int c = load_edge_idx(ei, is64, (long long)E + e);   // col = edge_index[1]
    atomicAdd(&g_deg[c], ew[e]);
    atomicAdd(&g_cnt[c], 1);
}

// ---------------- kernel 3: dinv ----------------
__global__ void k_dinv() {
    int i = blockIdx.x * blockDim.x + threadIdx.x;
    if (i >= NN) return;
    float d = g_deg[i];
    g_dinv[i] = (d > 0.f) ? rsqrtf(d) : 0.f;
}

// ---------------- kernel 4: exclusive scan of counts (single block, 1024 thr) ----------------
__global__ void k_scan() {
    const int PER = 10;                  // 1024*10 = 10240 >= NN+1
    int t = threadIdx.x;
    int lane = t & 31, w = t >> 5;
    int local[PER];
    int sum = 0;
#pragma unroll
    for (int p = 0; p < PER; ++p) {
        int idx = t * PER + p;
        int v = (idx < NN) ? g_cnt[idx] : 0;
        local[p] = sum;
        sum += v;
    }
    // inclusive warp scan of per-thread sums
    int x = sum;
#pragma unroll
    for (int o = 1; o < 32; o <<= 1) {
        int y = __shfl_up_sync(0xFFFFFFFFu, x, o);
        if (lane >= o) x += y;
    }
    __shared__ int ws[32];
    if (lane == 31) ws[w] = x;
    __syncthreads();
    if (w == 0) {
        int v = ws[lane];
#pragma unroll
        for (int o = 1; o < 32; o <<= 1) {
            int y = __shfl_up_sync(0xFFFFFFFFu, v, o);
            if (lane >= o) v += y;
        }
        ws[lane] = v;   // inclusive scan over warp totals
    }
    __syncthreads();
    int base = (x - sum) + (w > 0 ? ws[w - 1] : 0);
#pragma unroll
    for (int p = 0; p < PER; ++p) {
        int idx = t * PER + p;
        if (idx <= NN) g_base[idx] = base + local[p];
    }
}

// ---------------- kernel 5: fill CSR buckets ----------------
__global__ void k_fill(const void* __restrict__ ei, const float* __restrict__ ew, int E) {
    int e = blockIdx.x * blockDim.x + threadIdx.x;
    if (e >= E) return;
    int is64 = g_is64;
    int r = load_edge_idx(ei, is64, e);
    int c = load_edge_idx(ei, is64, (long long)E + e);
    float wv = ew[e] * g_dinv[r] * g_dinv[c];
    int pos = atomicAdd(&g_cursor[c], 1);
    int idx = g_base[c] + pos;
    g_sr[idx] = r;
    g_sw[idx] = wv;
}

// ---------------- kernel 6: GEMM h = x @ W_conv  (TF32 mma, cp.async double-buffered) ----------------
// Tiles: BM=64, BN=128(full), BK=32. 256 threads = 8 warps (2 along M x 4 along N).
#define BM 64
#define BK 32
#define XS_STRIDE 36
#define WS_STRIDE 132
#define XS_ELEMS (BM * XS_STRIDE)        // 2304
#define WS_ELEMS (BK * WS_STRIDE)        // 4224
#define GEMM_SMEM_BYTES ((2 * XS_ELEMS + 2 * WS_ELEMS) * 4)   // 52224

__device__ __forceinline__ void gemm_load(float* xs, float* ws,
                                          const float* __restrict__ X,
                                          const float* __restrict__ W,
                                          int blockRow, int kt, int tid) {
    // X tile: 64 rows x 32 cols (floats). 256 threads * 2 x float4 each.
    int rx = tid >> 3;
    int cx = (tid & 7) * 4;
#pragma unroll
    for (int h = 0; h < 2; ++h) {
        int row = rx + h * 32;
        int grow = blockRow + row;
        int gk = kt + cx;
        int ok = (grow < NN && gk < INF) ? 16 : 0;
        const float* src = ok ? (X + (size_t)grow * INF + gk) : X;
        cp_async16(xs + row * XS_STRIDE + cx, src, ok);
    }
    // W tile: 32 rows x 128 cols. 256 threads * 4 x float4 each.
    int kw = tid >> 5;
    int nw = (tid & 31) * 4;
#pragma unroll
    for (int h = 0; h < 4; ++h) {
        int kr = kw + h * 8;
        int gk = kt + kr;
        int ok = (gk < INF) ? 16 : 0;
        const float* src = ok ? (W + (size_t)gk * HID + nw) : W;
        cp_async16(ws + kr * WS_STRIDE + nw, src, ok);
    }
}

__global__ void k_gemm(const float* __restrict__ X, const float* __restrict__ W) {
    extern __shared__ float smem[];
    float* xs0 = smem;
    float* ws0 = smem + 2 * XS_ELEMS;

    int tid = threadIdx.x;
    int lane = tid & 31;
    int wid = tid >> 5;
    int wm = wid & 1;        // 2 warps along M (32 rows each)
    int wn = wid >> 1;       // 4 warps along N (32 cols each)
    int g = lane >> 2;       // groupID
    int tg = lane & 3;       // thread-in-group

    int blockRow = blockIdx.x * BM;
    const int NT = (INF + BK - 1) / BK;   // 313

    float acc[2][4][4];
#pragma unroll
    for (int mt = 0; mt < 2; ++mt)
#pragma unroll
        for (int nt = 0; nt < 4; ++nt)
#pragma unroll
            for (int q = 0; q < 4; ++q) acc[mt][nt][q] = 0.f;

    // prologue
    gemm_load(xs0, ws0, X, W, blockRow, 0, tid);
    asm volatile("cp.async.commit_group;\n" ::: "memory");

    for (int t = 0; t < NT; ++t) {
        int buf = t & 1;
        if (t + 1 < NT) {
            int nbuf = (t + 1) & 1;
            gemm_load(xs0 + nbuf * XS_ELEMS, ws0 + nbuf * WS_ELEMS, X, W, blockRow, (t + 1) * BK, tid);
            asm volatile("cp.async.commit_group;\n" ::: "memory");
            asm volatile("cp.async.wait_group 1;\n" ::: "memory");
        } else {
            asm volatile("cp.async.wait_group 0;\n" ::: "memory");
        }
        __syncthreads();

        const float* xs = xs0 + buf * XS_ELEMS;
        const float* ws = ws0 + buf * WS_ELEMS;

#pragma unroll
        for (int ks = 0; ks < 4; ++ks) {
            int k0 = ks * 8;
            unsigned A[2][4];
#pragma unroll
            for (int mt = 0; mt < 2; ++mt) {
                int r0 = wm * 32 + mt * 16 + g;
                A[mt][0] = f2tf(xs[r0 * XS_STRIDE + k0 + tg]);
                A[mt][1] = f2tf(xs[(r0 + 8) * XS_STRIDE + k0 + tg]);
                A[mt][2] = f2tf(xs[r0 * XS_STRIDE + k0 + tg + 4]);
                A[mt][3] = f2tf(xs[(r0 + 8) * XS_STRIDE + k0 + tg + 4]);
            }
            unsigned B[4][2];
#pragma unroll
            for (int nt = 0; nt < 4; ++nt) {
                int nc = wn * 32 + nt * 8 + g;
                B[nt][0] = f2tf(ws[(k0 + tg) * WS_STRIDE + nc]);
                B[nt][1] = f2tf(ws[(k0 + tg + 4) * WS_STRIDE + nc]);
            }
#pragma unroll
            for (int mt = 0; mt < 2; ++mt)
#pragma unroll
                for (int nt = 0; nt < 4; ++nt)
                    mma_tf32(acc[mt][nt], A[mt], B[nt]);
        }
        __syncthreads();
    }

    // epilogue: write h
#pragma unroll
    for (int mt = 0; mt < 2; ++mt) {
#pragma unroll
        for (int nt = 0; nt < 4; ++nt) {
            int r0 = blockRow + wm * 32 + mt * 16 + g;
            int col = wn * 32 + nt * 8 + tg * 2;
            if (r0 < NN)
                *(float2*)&g_h[(size_t)r0 * HID + col] = make_float2(acc[mt][nt][0], acc[mt][nt][1]);
            int r1 = r0 + 8;
            if (r1 < NN)
                *(float2*)&g_h[(size_t)r1 * HID + col] = make_float2(acc[mt][nt][2], acc[mt][nt][3]);
        }
    }
}

// ---------------- kernel 7: fused aggregation + bias + ReLU + linear + softmax ----------------
// One 128-thread block per node. h is L2-resident (5.1 MB), gathers hit L2.
__global__ void k_agg_final(const float* __restrict__ b_conv,
                            const float* __restrict__ W_lin,
                            const float* __restrict__ b_lin,
                            float* __restrict__ out) {
    int i = blockIdx.x;
    int j = threadIdx.x;
    int lane = j & 31, w = j >> 5;

    int s = g_base[i];
    int e2 = g_base[i + 1];
    float di = g_dinv[i];
    float acc = g_h[(size_t)i * HID + j] * di * di;   // self loop: dinv[i]*1*dinv[i]

    for (int p = s; p < e2; ++p) {
        int r = g_sr[p];
        float wv = g_sw[p];
        acc = fmaf(wv, g_h[(size_t)r * HID + j], acc);
    }

    float v = fmaxf(acc + b_conv[j], 0.f);
    float l0 = v * W_lin[j * 2 + 0];
    float l1 = v * W_lin[j * 2 + 1];
#pragma unroll
    for (int o = 16; o > 0; o >>= 1) {
        l0 += __shfl_xor_sync(0xFFFFFFFFu, l0, o);
        l1 += __shfl_xor_sync(0xFFFFFFFFu, l1, o);
    }
    __shared__ float s0[4], s1[4];
    if (lane == 0) { s0[w] = l0; s1[w] = l1; }
    __syncthreads();
    if (j == 0) {
        float L0 = s0[0] + s0[1] + s0[2] + s0[3] + b_lin[0];
        float L1 = s1[0] + s1[1] + s1[2] + s1[3] + b_lin[1];
        float m = fmaxf(L0, L1);
        float e0 = expf(L0 - m), e1 = expf(L1 - m);
        float inv = 1.f / (e0 + e1);
        out[i * 2 + 0] = e0 * inv;
        out[i * 2 + 1] = e1 * inv;
    }
}

// ---------------- launcher ----------------
extern "C" void kernel_launch(void* const* d_in, const int* in_sizes, int n_in,
                              void* d_out, int out_size) {
    const float* x  = (const float*)d_in[0];
    const void*  ei = d_in[1];
    const float* ew = (const float*)d_in[2];
    const float* Wc = (const float*)d_in[3];
    const float* bc = (const float*)d_in[4];
    const float* Wl = (const float*)d_in[5];
    const float* bl = (const float*)d_in[6];
    float*       out = (float*)d_out;
    int E = in_sizes[2];

    k_init<<<(NN + 255) / 256, 256>>>();
    k_detect<<<(E + 255) / 256, 256>>>((const int*)ei, E);
    k_count<<<(E + 255) / 256, 256>>>(ei, ew, E);
    k_dinv<<<(NN + 255) / 256, 256>>>();
    k_scan<<<1, 1024>>>();
    k_fill<<<(E + 255) / 256, 256>>>(ei, ew, E);

    cudaFuncSetAttribute(k_gemm, cudaFuncAttributeMaxDynamicSharedMemorySize, GEMM_SMEM_BYTES);
    k_gemm<<<(NN + BM - 1) / BM, 256, GEMM_SMEM_BYTES>>>(x, Wc);

    k_agg_final<<<NN, 128>>>(bc, Wl, bl, out);

    (void)n_in; (void)out_size;
}